// round 10
// baseline (speedup 1.0000x reference)
#include <cuda_runtime.h>
#include <math.h>

#define NPTS   8192
#define BATCH  2
#define NQ     (2 * BATCH * NPTS)    // 32768 queries (both directions)
#define G      64
#define G3     (G * G * G)
#define K      12                    // slots per cell
#define H      0.125f
#define INVH   8.0f
#define LOF    (-4.0f)
#define CLOSE1 (H * H)               // close after rings 0-1
#define CLOSE2 (4.0f * H * H)        // close after ring 2

// Scratch (__device__ globals per harness rules)
__device__ int            g_count[4][G3];        // 4 MB: [side*2+b]
__device__ unsigned short g_cells[4][G3][K];     // ~25 MB point indices
__device__ float          g_qmin[NQ];            // squared min distances
__device__ int            g_fb_count;
__device__ int            g_fb_list[NQ];
__device__ float          g_bsum[128];

static __device__ __forceinline__ int clampi(int v, int lo, int hi) {
    return v < lo ? lo : (v > hi ? hi : v);
}

// Fill the 4 grids: regions 0,1 = pred (b=0,1); 2,3 = gt.
__global__ void __launch_bounds__(256)
build_kernel(const float* __restrict__ pred, const float* __restrict__ gt) {
    int tid = blockIdx.x * 256 + threadIdx.x;       // 0..65535
    int reg = tid >> 14;                            // 0..3
    int b   = (tid >> 13) & 1;
    int n   = tid & (NPTS - 1);
    const float* src = (reg < 2) ? pred : gt;
    const float* p = src + ((long)(b * NPTS + n)) * 3;
    float x = p[0], y = p[1], z = p[2];
    int cx = clampi((int)floorf((x - LOF) * INVH), 0, G - 1);
    int cy = clampi((int)floorf((y - LOF) * INVH), 0, G - 1);
    int cz = clampi((int)floorf((z - LOF) * INVH), 0, G - 1);
    int cid = (cz * G + cy) * G + cx;
    int slot = atomicAdd(&g_count[reg][cid], 1);
    if (slot < K) g_cells[reg][cid][slot] = (unsigned short)n;
}

// One thread per query: rings 0-1, optional ring 2, else flag for fallback.
__global__ void __launch_bounds__(256)
query_kernel(const float* __restrict__ pred, const float* __restrict__ gt) {
    int q = blockIdx.x * 256 + threadIdx.x;          // 0..32767
    int side = q >> 14;                              // 0: gt queries, 1: pred queries
    int b    = (q >> 13) & 1;
    int n    = q & (NPTS - 1);
    const float* qsrc = (side == 0) ? gt : pred;
    const float* db   = (side == 0) ? pred : gt;
    int reg = (side == 0) ? b : 2 + b;               // grid of the DB side

    const float* qp = qsrc + ((long)(b * NPTS + n)) * 3;
    float qx = qp[0], qy = qp[1], qz = qp[2];
    int cx = clampi((int)floorf((qx - LOF) * INVH), 0, G - 1);
    int cy = clampi((int)floorf((qy - LOF) * INVH), 0, G - 1);
    int cz = clampi((int)floorf((qz - LOF) * INVH), 0, G - 1);

    float best = 3.4e38f;
    bool flag = false;

    // ---- Stage A: rings 0-1 (3^3 box). Prefetch counts for MLP. ----
    int cnt[27];
#pragma unroll
    for (int dz = -1; dz <= 1; dz++)
#pragma unroll
        for (int dy = -1; dy <= 1; dy++)
#pragma unroll
            for (int dx = -1; dx <= 1; dx++) {
                int i = (dz + 1) * 9 + (dy + 1) * 3 + (dx + 1);
                int x = cx + dx, y = cy + dy, z = cz + dz;
                bool ok = ((unsigned)x < G) & ((unsigned)y < G) & ((unsigned)z < G);
                cnt[i] = ok ? g_count[reg][(z * G + y) * G + x] : 0;
            }
#pragma unroll
    for (int dz = -1; dz <= 1; dz++)
#pragma unroll
        for (int dy = -1; dy <= 1; dy++)
#pragma unroll
            for (int dx = -1; dx <= 1; dx++) {
                int i = (dz + 1) * 9 + (dy + 1) * 3 + (dx + 1);
                int c = cnt[i];
                if (c == 0) continue;
                flag |= (c > K);
                int nn = c < K ? c : K;
                int cid = ((cz + dz) * G + (cy + dy)) * G + (cx + dx);
                for (int s = 0; s < nn; s++) {
                    int idx = g_cells[reg][cid][s];
                    const float* p = db + ((long)(b * NPTS + idx)) * 3;
                    float ddx = p[0] - qx, ddy = p[1] - qy, ddz = p[2] - qz;
                    float d2 = fmaf(ddx, ddx, fmaf(ddy, ddy, ddz * ddz));
                    best = fminf(best, d2);
                }
            }

    // ---- Stage B: ring 2 shell, with per-cell box-bound pruning. ----
    if (best > CLOSE1) {
        for (int dz = -2; dz <= 2; dz++) {
            int z = cz + dz;
            if ((unsigned)z >= G) continue;
            int az = dz < 0 ? -dz : dz;
            for (int dy = -2; dy <= 2; dy++) {
                int y = cy + dy;
                if ((unsigned)y >= G) continue;
                int ay = dy < 0 ? -dy : dy;
                for (int dx = -2; dx <= 2; dx++) {
                    int m = az;
                    int ay2 = ay, ax = dx < 0 ? -dx : dx;
                    if (ay2 > m) m = ay2;
                    if (ax > m) m = ax;
                    if (m != 2) continue;               // shell only
                    int x = cx + dx;
                    if ((unsigned)x >= G) continue;
                    // lower bound: distance from q to the cell box
                    float clo = LOF + x * H, chi = clo + H;
                    float bx = fmaxf(0.f, fmaxf(clo - qx, qx - chi));
                    float ylo = LOF + y * H, yhi = ylo + H;
                    float by = fmaxf(0.f, fmaxf(ylo - qy, qy - yhi));
                    float zlo = LOF + z * H, zhi = zlo + H;
                    float bz = fmaxf(0.f, fmaxf(zlo - qz, qz - zhi));
                    float d2c = fmaf(bx, bx, fmaf(by, by, bz * bz));
                    if (d2c >= best) continue;
                    int cid = (z * G + y) * G + x;
                    int c = g_count[reg][cid];
                    if (c == 0) continue;
                    flag |= (c > K);
                    int nn = c < K ? c : K;
                    for (int s = 0; s < nn; s++) {
                        int idx = g_cells[reg][cid][s];
                        const float* p = db + ((long)(b * NPTS + idx)) * 3;
                        float ddx = p[0] - qx, ddy = p[1] - qy, ddz = p[2] - qz;
                        float d2 = fmaf(ddx, ddx, fmaf(ddy, ddy, ddz * ddz));
                        best = fminf(best, d2);
                    }
                }
            }
        }
    }

    g_qmin[q] = best;
    // Exactness guard: unclosed or overflow-tainted queries go to brute force.
    if (flag || best > CLOSE2) {
        int pos = atomicAdd(&g_fb_count, 1);
        g_fb_list[pos] = q;
    }
}

// Exact brute force for flagged queries: one block per entry (grid-stride).
__global__ void __launch_bounds__(256)
fallback_kernel(const float* __restrict__ pred, const float* __restrict__ gt) {
    __shared__ float sb[256];
    int nfb = g_fb_count;
    for (int fi = blockIdx.x; fi < nfb; fi += gridDim.x) {
        int q = g_fb_list[fi];
        int side = q >> 14;
        int b    = (q >> 13) & 1;
        int n    = q & (NPTS - 1);
        const float* qsrc = (side == 0) ? gt : pred;
        const float* db   = (side == 0) ? pred : gt;
        const float* qp = qsrc + ((long)(b * NPTS + n)) * 3;
        float qx = qp[0], qy = qp[1], qz = qp[2];

        float best = 3.4e38f;
        for (int j = threadIdx.x; j < NPTS; j += 256) {
            const float* p = db + ((long)(b * NPTS + j)) * 3;
            float ddx = p[0] - qx, ddy = p[1] - qy, ddz = p[2] - qz;
            best = fminf(best, fmaf(ddx, ddx, fmaf(ddy, ddy, ddz * ddz)));
        }
        sb[threadIdx.x] = best;
        __syncthreads();
        for (int off = 128; off > 0; off >>= 1) {
            if (threadIdx.x < off)
                sb[threadIdx.x] = fminf(sb[threadIdx.x], sb[threadIdx.x + off]);
            __syncthreads();
        }
        if (threadIdx.x == 0) g_qmin[q] = sb[0];
        __syncthreads();
    }
}

// Parallel sum of sqrt(min^2): 128 blocks then 1 block.
__global__ void __launch_bounds__(256)
reduce2_kernel() {
    int idx = blockIdx.x * 256 + threadIdx.x;
    float s = sqrtf(fmaxf(g_qmin[idx], 0.0f));
    __shared__ float sb[256];
    sb[threadIdx.x] = s;
    __syncthreads();
    for (int off = 128; off > 0; off >>= 1) {
        if (threadIdx.x < off) sb[threadIdx.x] += sb[threadIdx.x + off];
        __syncthreads();
    }
    if (threadIdx.x == 0) g_bsum[blockIdx.x] = sb[0];
}

__global__ void __launch_bounds__(128)
reduce3_kernel(float* __restrict__ out) {
    __shared__ float sb[128];
    sb[threadIdx.x] = g_bsum[threadIdx.x];
    __syncthreads();
    for (int off = 64; off > 0; off >>= 1) {
        if (threadIdx.x < off) sb[threadIdx.x] += sb[threadIdx.x + off];
        __syncthreads();
    }
    if (threadIdx.x == 0) out[0] = sb[0] / (float)(BATCH * NPTS);
}

extern "C" void kernel_launch(void* const* d_in, const int* in_sizes, int n_in,
                              void* d_out, int out_size) {
    const float* pred = (const float*)d_in[0];
    const float* gt   = (const float*)d_in[1];
    float* out = (float*)d_out;

    void* cnt_ptr = 0; void* fbc_ptr = 0;
    cudaGetSymbolAddress(&cnt_ptr, g_count);
    cudaGetSymbolAddress(&fbc_ptr, g_fb_count);
    cudaMemsetAsync(cnt_ptr, 0, sizeof(int) * 4 * G3);
    cudaMemsetAsync(fbc_ptr, 0, sizeof(int));

    build_kernel<<<256, 256>>>(pred, gt);
    query_kernel<<<128, 256>>>(pred, gt);
    fallback_kernel<<<256, 256>>>(pred, gt);
    reduce2_kernel<<<128, 256>>>();
    reduce3_kernel<<<1, 128>>>(out);
}

// round 11
// speedup vs baseline: 3.3390x; 3.3390x over previous
#include <cuda_runtime.h>
#include <math.h>

#define NPTS   8192
#define BATCH  2
#define TI     128                  // rows per block tile
#define TJ     1024                 // cols per block tile
#define IT     (NPTS / TI)          // 64 row tiles
#define JT     (NPTS / TJ)          // 8 col tiles
#define THREADS 256
#define IR     8                    // rows per thread (ty: 16 groups)
#define CPP    16                   // col-pair iterations per phase
#define NPHASE 2                    // 2 phases x 512 cols
#define CRP    520                  // colred row pitch (512 + pad)
#define FPSCALE 17592186044416.0    // 2^44 fixed-point scale

// Global min bits: [side][b][n]; side 0 = gt rows (dist1), 1 = pred cols (dist2).
__device__ unsigned int g_minbits[2 * BATCH * NPTS];
__device__ unsigned long long g_acc;     // fixed-point sum (deterministic)
__device__ unsigned int g_done;          // completed-block counter

// ---- packed f32x2 helpers --------------------------------------------------
union f2u { unsigned long long u; float2 f; };
static __device__ __forceinline__ unsigned long long pack2(float lo, float hi) {
    f2u v; v.f = make_float2(lo, hi); return v.u;
}
static __device__ __forceinline__ unsigned long long fma2(
    unsigned long long a, unsigned long long b, unsigned long long c) {
    unsigned long long d;
    asm("fma.rn.f32x2 %0, %1, %2, %3;" : "=l"(d) : "l"(a), "l"(b), "l"(c));
    return d;
}
static __device__ __forceinline__ unsigned long long add2(
    unsigned long long a, unsigned long long b) {
    unsigned long long d;
    asm("add.rn.f32x2 %0, %1, %2;" : "=l"(d) : "l"(a), "l"(b));
    return d;
}
static __device__ __forceinline__ unsigned int enc_f(float f) {
    unsigned int u = __float_as_uint(f);
    return (u & 0x80000000u) ? ~u : (u | 0x80000000u);
}
static __device__ __forceinline__ float dec_f(unsigned int u) {
    u = (u & 0x80000000u) ? (u ^ 0x80000000u) : ~u;
    return __uint_as_float(u);
}

// Grid (IT, JT, BATCH). Tile: 128 gt-rows x 1024 pred-cols.
// s_ij = g2_i + p2_j - 2<g_i,p_j>; row-min and col-min -> atomicMin epilogue.
__global__ void __launch_bounds__(THREADS, 4)
fused_kernel(const float* __restrict__ pred, const float* __restrict__ gt) {
    __shared__ float4 qrow[TI];          // (x, y, z, g2)              2 KB
    __shared__ float4 colA[TJ / 2];      // {-2x0,-2x1,-2y0,-2y1}      8 KB
    __shared__ float4 colB[TJ / 2];      // {-2z0,-2z1,  w0,  w1}      8 KB
    __shared__ float  colred[8][CRP];    // per-warp col mins        ~16.3 KB

    int it = blockIdx.x, jt = blockIdx.y, b = blockIdx.z;
    int tid = threadIdx.x;

    for (int i = tid; i < TI; i += THREADS) {
        const float* g = gt + (long)(b * NPTS + it * TI + i) * 3;
        float x = g[0], y = g[1], z = g[2];
        qrow[i] = make_float4(x, y, z, x * x + y * y + z * z);
    }
    for (int p = tid; p < TJ / 2; p += THREADS) {
        const float* q = pred + (long)(b * NPTS + jt * TJ + 2 * p) * 3;
        float x0 = q[0], y0 = q[1], z0 = q[2];
        float x1 = q[3], y1 = q[4], z1 = q[5];
        colA[p] = make_float4(-2.f * x0, -2.f * x1, -2.f * y0, -2.f * y1);
        colB[p] = make_float4(-2.f * z0, -2.f * z1,
                              x0 * x0 + y0 * y0 + z0 * z0,
                              x1 * x1 + y1 * y1 + z1 * z1);
    }
    __syncthreads();

    int ty = tid >> 4, tx = tid & 15;
    int warp = tid >> 5;

    unsigned long long qxd[IR], qyd[IR], qzd[IR], g22[IR];
    float rowacc[IR];
#pragma unroll
    for (int r = 0; r < IR; r++) {
        float4 q = qrow[ty * IR + r];
        qxd[r] = pack2(q.x, q.x); qyd[r] = pack2(q.y, q.y);
        qzd[r] = pack2(q.z, q.z); g22[r] = pack2(q.w, q.w);
        rowacc[r] = 3.4e38f;
    }

    const ulonglong2* cA = (const ulonglong2*)colA;
    const ulonglong2* cB = (const ulonglong2*)colB;

    for (int phase = 0; phase < NPHASE; phase++) {
#pragma unroll 4
        for (int cp = 0; cp < CPP; cp++) {
            int p = phase * 256 + cp * 16 + tx;   // lanes: consecutive 16B chunks
            ulonglong2 P0 = cA[p];
            ulonglong2 P1 = cB[p];
            float clo = 3.4e38f, chi = 3.4e38f;
#pragma unroll
            for (int r = 0; r < IR; r++) {
                unsigned long long t =
                    fma2(qxd[r], P0.x, fma2(qyd[r], P0.y, fma2(qzd[r], P1.x, P1.y)));
                f2u s; s.u = add2(t, g22[r]);
                float slo = s.f.x, shi = s.f.y;
                rowacc[r] = fminf(rowacc[r], fminf(slo, shi));
                clo = fminf(clo, slo);
                chi = fminf(chi, shi);
            }
            // warp halves (ty g, g+1) cover the same cols: combine via xor 16
            clo = fminf(clo, __shfl_xor_sync(0xffffffffu, clo, 16));
            chi = fminf(chi, __shfl_xor_sync(0xffffffffu, chi, 16));
            if ((tid & 31) < 16)
                *(float2*)&colred[warp][2 * (cp * 16 + tx)] = make_float2(clo, chi);
        }
        __syncthreads();
        // Flush this phase's 512 columns: min over 8 warp slices -> atomicMin
        for (int s0 = tid; s0 < 512; s0 += THREADS) {
            float m = colred[0][s0];
#pragma unroll
            for (int w = 1; w < 8; w++) m = fminf(m, colred[w][s0]);
            int col = jt * TJ + phase * 512 + s0;
            atomicMin(&g_minbits[(BATCH * NPTS) + (b << 13) + col], enc_f(m));
        }
        __syncthreads();
    }

    // Row mins: butterfly over the 16 tx lanes (masks stay inside halves).
#pragma unroll
    for (int r = 0; r < IR; r++) {
        float v = rowacc[r];
        v = fminf(v, __shfl_xor_sync(0xffffffffu, v, 1));
        v = fminf(v, __shfl_xor_sync(0xffffffffu, v, 2));
        v = fminf(v, __shfl_xor_sync(0xffffffffu, v, 4));
        v = fminf(v, __shfl_xor_sync(0xffffffffu, v, 8));
        if (tx == 0)
            atomicMin(&g_minbits[(b << 13) + it * TI + ty * IR + r], enc_f(v));
    }
}

// Single reduce: 128 blocks; per-block float tree sum -> fixed-point u64
// atomicAdd (associative -> deterministic); last block writes the scalar.
__global__ void __launch_bounds__(256)
reduce_kernel(float* __restrict__ out) {
    int idx = blockIdx.x * 256 + threadIdx.x;   // < 32768
    float m = dec_f(g_minbits[idx]);
    float s = sqrtf(fmaxf(m, 0.0f));

    __shared__ float sb[256];
    sb[threadIdx.x] = s;
    __syncthreads();
    for (int off = 128; off > 0; off >>= 1) {
        if (threadIdx.x < off) sb[threadIdx.x] += sb[threadIdx.x + off];
        __syncthreads();
    }
    if (threadIdx.x == 0) {
        unsigned long long fx = (unsigned long long)((double)sb[0] * FPSCALE);
        atomicAdd(&g_acc, fx);
        __threadfence();
        unsigned int done = atomicAdd(&g_done, 1u);
        if (done == 127u) {   // last block: all adds visible
            unsigned long long acc = *(volatile unsigned long long*)&g_acc;
            out[0] = (float)((double)acc / FPSCALE / (double)(BATCH * NPTS));
        }
    }
}

extern "C" void kernel_launch(void* const* d_in, const int* in_sizes, int n_in,
                              void* d_out, int out_size) {
    const float* pred = (const float*)d_in[0];
    const float* gt   = (const float*)d_in[1];
    float* out = (float*)d_out;

    void* mb_ptr = 0; void* acc_ptr = 0; void* done_ptr = 0;
    cudaGetSymbolAddress(&mb_ptr, g_minbits);
    cudaGetSymbolAddress(&acc_ptr, g_acc);
    cudaGetSymbolAddress(&done_ptr, g_done);
    cudaMemsetAsync(mb_ptr, 0xFF, sizeof(unsigned int) * 2 * BATCH * NPTS);
    cudaMemsetAsync(acc_ptr, 0, sizeof(unsigned long long));
    cudaMemsetAsync(done_ptr, 0, sizeof(unsigned int));

    dim3 grid(IT, JT, BATCH);
    fused_kernel<<<grid, THREADS>>>(pred, gt);
    reduce_kernel<<<128, 256>>>(out);
}